// round 9
// baseline (speedup 1.0000x reference)
#include <cuda_runtime.h>

#define BB 16
#define EE 128
#define CC 512
#define NCL 5
#define KITERS 8    // truncation 0.2^9/0.8 ~ 6.5e-7 << 1e-3 gate

// ---------------- device scratch (no allocations allowed) ----------------
__device__ float  g_part[4*BB*EE*EE];   // 4-way k-split partial Grams
__device__ float  g_sqdist[BB*EE*EE];   // scaled sq_dist matrix
__device__ double g_psum[128];
__device__ double g_psq[128];
__device__ int    g_lbl64;              // 1 if labels buffer is int64

// ---------------- f32x2 packed helpers (Blackwell) ----------------
__device__ __forceinline__ unsigned long long pk2(float a, float b) {
    unsigned long long r;
    asm("mov.b64 %0, {%1,%2};" : "=l"(r) : "f"(a), "f"(b));
    return r;
}
__device__ __forceinline__ void unpk2(unsigned long long v, float& lo, float& hi) {
    asm("mov.b64 {%0,%1}, %2;" : "=f"(lo), "=f"(hi) : "l"(v));
}
__device__ __forceinline__ void fma2(unsigned long long& acc,
                                     unsigned long long a, unsigned long long b) {
    asm("fma.rn.f32x2 %0, %1, %2, %0;" : "+l"(acc) : "l"(a), "l"(b));
}
__device__ __forceinline__ unsigned long long add2(unsigned long long a,
                                                   unsigned long long b) {
    unsigned long long r;
    asm("add.rn.f32x2 %0, %1, %2;" : "=l"(r) : "l"(a), "l"(b));
    return r;
}

// ================= K1: partial Gram, symmetric, 64x64 tile =============
// grid (3 tiles, 64 = b*4+kc), 256 threads (16x16), 4x4/thread, f32x2.
// tiles: 0 -> (ib=0,jb=0), 1 -> (64,64), 2 -> (0,64) + transpose store.
// __launch_bounds__(256,2) caps regs at 128 -> 2 blocks/SM resident.
// smem float2 tiles [64][32], XOR-swizzled: phys c2' = c2 ^ ((row>>2)&15)
__global__ void __launch_bounds__(256, 2) k_gram(const float* __restrict__ x,
                                                 const int* __restrict__ lab32) {
    __shared__ float2 sxi[64][32];
    __shared__ float2 sxj[64][32];
    int t  = threadIdx.x;
    int tx = t & 15, ty = t >> 4;
    int b  = blockIdx.y >> 2, kc = blockIdx.y & 3;
    int tile = blockIdx.x;                 // 0,1,2
    int ib = (tile == 1) ? 64 : 0;
    int jb = (tile == 0) ? 0  : 64;
    const float* xb = x + (size_t)b * EE * CC;

    // labels dtype detection (one block): int64 => odd 32-bit words all 0
    if (blockIdx.x == 0 && blockIdx.y == 0) {
        __shared__ int sflag;
        if (t == 0) sflag = 0;
        __syncthreads();
        int v = 0;
        #pragma unroll
        for (int k = 0; k < 4; k++) v |= lab32[2*(t + 256*k) + 1];
        if (v) sflag = 1;
        __syncthreads();
        if (t == 0) g_lbl64 = (sflag == 0);
        __syncthreads();
    }

    unsigned long long acc[4][4];
    #pragma unroll
    for (int r = 0; r < 4; r++)
        #pragma unroll
        for (int s = 0; s < 4; s++) acc[r][s] = 0ull;

    for (int chunk = 0; chunk < 2; chunk++) {
        int ch0 = kc * 128 + chunk * 64;
        #pragma unroll
        for (int k = 0; k < 8; k++) {
            int idx = t + k * 256;           // 2048 float2 per tile
            int row = idx >> 5, c2 = idx & 31;
            int sw  = c2 ^ ((row >> 2) & 15);
            sxi[row][sw] = *(const float2*)&xb[(ib + row) * CC + ch0 + c2 * 2];
            sxj[row][sw] = *(const float2*)&xb[(jb + row) * CC + ch0 + c2 * 2];
        }
        __syncthreads();
        #pragma unroll
        for (int c2 = 0; c2 < 32; c2++) {
            unsigned long long a2[4], b2[4];
            int ca = c2 ^ ty, cb = c2 ^ tx;
            #pragma unroll
            for (int r = 0; r < 4; r++) a2[r] = *(const unsigned long long*)&sxi[4*ty + r][ca];
            #pragma unroll
            for (int s = 0; s < 4; s++) b2[s] = *(const unsigned long long*)&sxj[4*tx + s][cb];
            #pragma unroll
            for (int r = 0; r < 4; r++)
                #pragma unroll
                for (int s = 0; s < 4; s++) fma2(acc[r][s], a2[r], b2[s]);
        }
        __syncthreads();
    }

    // reduce f32x2 pairs -> scalars
    float g[4][4];
    #pragma unroll
    for (int r = 0; r < 4; r++)
        #pragma unroll
        for (int s = 0; s < 4; s++) {
            float lo, hi; unpk2(acc[r][s], lo, hi); g[r][s] = lo + hi;
        }

    float* plane = g_part + (size_t)(kc * BB + b) * EE * EE;
    float* dst = plane + (size_t)(ib + 4*ty) * EE + jb + 4*tx;
    #pragma unroll
    for (int r = 0; r < 4; r++)
        *(float4*)(dst + (size_t)r * EE) = make_float4(g[r][0], g[r][1], g[r][2], g[r][3]);

    if (tile == 2) {   // mirror: G[jb+4tx+s][ib+4ty+r] = g[r][s]
        float* dstT = plane + (size_t)(jb + 4*tx) * EE + ib + 4*ty;
        #pragma unroll
        for (int s = 0; s < 4; s++)
            *(float4*)(dstT + (size_t)s * EE) = make_float4(g[0][s], g[1][s], g[2][s], g[3][s]);
    }
}

// ================= K2: combine partials -> sq_dist + stats partials ====
// grid (8 rowgroups, 16 batches) = 128 blocks, 512 thr: warp = row.
__global__ void __launch_bounds__(512) k_sd() {
    __shared__ float  diag[EE];
    __shared__ double sred[16], qred[16];
    int t = threadIdx.x;
    int b = blockIdx.y, rg = blockIdx.x;
    int w = t >> 5, lane = t & 31;
    int i = rg * 16 + w;
    const float rsc = 0.04419417382415922f;   // 1/sqrt(512)

    const float* gp0 = g_part + (size_t)(0*BB + b) * EE * EE;
    const float* gp1 = g_part + (size_t)(1*BB + b) * EE * EE;
    const float* gp2 = g_part + (size_t)(2*BB + b) * EE * EE;
    const float* gp3 = g_part + (size_t)(3*BB + b) * EE * EE;

    if (t < EE) {
        size_t d = (size_t)t * EE + t;
        diag[t] = (gp0[d] + gp1[d]) + (gp2[d] + gp3[d]);
    }
    __syncthreads();

    float  ni = diag[i];
    double sm = 0.0, sq = 0.0;
    float* rowp = g_sqdist + (size_t)(b * EE + i) * EE;
    #pragma unroll
    for (int k = 0; k < 4; k++) {
        int j = lane + 32*k;
        size_t off = (size_t)i * EE + j;
        float G = (gp0[off] + gp1[off]) + (gp2[off] + gp3[off]);
        float sd = (ni + diag[j] - 2.f * G) * rsc;
        rowp[j] = sd;
        if (j != i) { double d = sd; sm += d; sq += d * d; }
    }
    #pragma unroll
    for (int o = 16; o; o >>= 1) {
        sm += __shfl_xor_sync(0xffffffffu, sm, o);
        sq += __shfl_xor_sync(0xffffffffu, sq, o);
    }
    if (lane == 0) { sred[w] = sm; qred[w] = sq; }
    __syncthreads();
    if (w == 0) {
        double s2 = (lane < 16) ? sred[lane] : 0.0;
        double q2 = (lane < 16) ? qred[lane] : 0.0;
        #pragma unroll
        for (int o = 8; o; o >>= 1) {
            s2 += __shfl_xor_sync(0xffffffffu, s2, o);
            q2 += __shfl_xor_sync(0xffffffffu, q2, o);
        }
        if (lane == 0) { g_psum[b * 8 + rg] = s2; g_psq[b * 8 + rg] = q2; }
    }
}

// ================= K3: stats + weights + rowsum + Neumann + output =====
// grid 16 (one batch per block), block 1024: thread = (row i, j-octant q).
#define VR 12
__global__ void __launch_bounds__(1024, 1)
k_prop(const int* __restrict__ lab32, float* __restrict__ out) {
    __shared__ __align__(16) float f[EE];
    __shared__ float sh_inv;
    __shared__ __align__(16) float rs_part[EE * 4];
    __shared__ __align__(16) float v[EE * VR];
    __shared__ __align__(16) float pbuf[7 * EE * 8];
    int b = blockIdx.x, t = threadIdx.x;
    int i = t & 127, q = t >> 7;           // q in 0..7
    int lane = t & 31, wq = (t >> 5) & 3;  // warp index within q-group
    int base = q * 16;

    // ---- 1/std from the 128 double partials (warp 0) ----
    if (t < 32) {
        double s2 = g_psum[t] + g_psum[t + 32] + g_psum[t + 64] + g_psum[t + 96];
        double q2 = g_psq[t]  + g_psq[t + 32]  + g_psq[t + 64]  + g_psq[t + 96];
        #pragma unroll
        for (int o = 16; o; o >>= 1) {
            s2 += __shfl_xor_sync(0xffffffffu, s2, o);
            q2 += __shfl_xor_sync(0xffffffffu, q2, o);
        }
        if (t == 0) {
            const double cnt = (double)BB * EE * (EE - 1);     // mask = off-diagonal
            double var = (q2 - s2 * s2 / cnt) / (cnt - 1.0);   // Bessel (ddof=1)
            sh_inv = (float)(1.0 / sqrt(var));
        }
    }
    __syncthreads();
    float inv = sh_inv;

    // ---- W entries for rows base..base+15, column i ----
    const float* Sb = g_sqdist + (size_t)b * EE * EE;
    float wv[16];
    #pragma unroll
    for (int jj = 0; jj < 16; jj++) {
        int j = base + jj;
        float sd = Sb[(size_t)j * EE + i];
        wv[jj] = (j == i) ? 0.f : expf(-sd * inv);
    }

    // ---- row sums: reduce wv over i (32 lanes, then 4 warps per q) ----
    #pragma unroll
    for (int jj = 0; jj < 16; jj++) {
        float r = wv[jj];
        #pragma unroll
        for (int o = 16; o; o >>= 1) r += __shfl_xor_sync(0xffffffffu, r, o);
        if (lane == 0) rs_part[(base + jj) * 4 + wq] = r;
    }
    __syncthreads();
    if (t < EE) {
        float4 p = *(const float4*)&rs_part[t * 4];
        f[t] = 0.2f / (1e-4f + (p.x + p.y + p.z + p.w));   // alpha folded in
    }
    __syncthreads();

    // ss[jj] packed {s,s}; s = alpha*S[i][base+jj] = W[base+jj][i]*f[base+jj]
    unsigned long long ss[16];
    #pragma unroll
    for (int jj = 0; jj < 16; jj++) {
        float sv = wv[jj] * f[base + jj];
        ss[jj] = pk2(sv, sv);
    }

    unsigned long long a01 = 0ull, a23 = 0ull, a45 = 0ull;
    if (q == 0) {
        int lbl = g_lbl64 ? lab32[2*(b*EE + i)] : lab32[b*EE + i];
        float vv[6];
        #pragma unroll
        for (int c = 0; c < NCL; c++) vv[c] = (lbl == c) ? 1.f : 0.f;
        vv[5] = 1.f;   // ones column -> L1 row norm of P (P >= 0)
        a01 = pk2(vv[0], vv[1]); a23 = pk2(vv[2], vv[3]); a45 = pk2(vv[4], vv[5]);
        *(ulonglong2*)&v[i*VR]     = make_ulonglong2(a01, a23);
        *(unsigned long long*)&v[i*VR + 4] = a45;
    }
    __syncthreads();

    for (int it = 0; it < KITERS; it++) {
        unsigned long long p01 = 0ull, p23 = 0ull, p45 = 0ull;
        #pragma unroll
        for (int jj = 0; jj < 16; jj++) {
            int j = base + jj;
            ulonglong2 wvd = *(const ulonglong2*)&v[j*VR];
            unsigned long long w2 = *(const unsigned long long*)&v[j*VR + 4];
            fma2(p01, ss[jj], wvd.x); fma2(p23, ss[jj], wvd.y); fma2(p45, ss[jj], w2);
        }
        if (q) {
            float* pb = &pbuf[((q - 1) * EE + i) * 8];
            *(ulonglong2*)pb = make_ulonglong2(p01, p23);
            *(unsigned long long*)(pb + 4) = p45;
        }
        __syncthreads();
        if (q == 0) {
            #pragma unroll
            for (int k = 0; k < 7; k++) {
                const float* pb = &pbuf[(k * EE + i) * 8];
                ulonglong2 r = *(const ulonglong2*)pb;
                unsigned long long r2 = *(const unsigned long long*)(pb + 4);
                p01 = add2(p01, r.x); p23 = add2(p23, r.y); p45 = add2(p45, r2);
            }
            a01 = add2(a01, p01); a23 = add2(a23, p23); a45 = add2(a45, p45);
            *(ulonglong2*)&v[i*VR]     = make_ulonglong2(p01, p23);
            *(unsigned long long*)&v[i*VR + 4] = p45;
        }
        __syncthreads();   // v fully updated before next iteration reads it
    }

    if (q == 0) {
        float y0, y1, y2, y3, y4, l1;
        unpk2(a01, y0, y1); unpk2(a23, y2, y3); unpk2(a45, y4, l1);
        float invl = 1.f / fmaxf(l1, 1e-12f);
        float* o = out + (size_t)(b*EE + i) * NCL;
        o[0] = logf(y0 * invl + 1e-6f);
        o[1] = logf(y1 * invl + 1e-6f);
        o[2] = logf(y2 * invl + 1e-6f);
        o[3] = logf(y3 * invl + 1e-6f);
        o[4] = logf(y4 * invl + 1e-6f);
    }
}

// ================= launcher =================
extern "C" void kernel_launch(void* const* d_in, const int* in_sizes, int n_in,
                              void* d_out, int out_size) {
    const float* x   = (const float*)d_in[0];
    const int*   lab = (const int*)d_in[1];   // int32 or int64 — detected on device
    float*       out = (float*)d_out;

    k_gram<<<dim3(3, 64), 256>>>(x, lab);
    k_sd<<<dim3(8, BB), 512>>>();
    k_prop<<<BB, 1024>>>(lab, out);
}

// round 10
// speedup vs baseline: 1.1550x; 1.1550x over previous
#include <cuda_runtime.h>

#define BB 16
#define EE 128
#define CC 512
#define NCL 5
#define KITERS 8    // truncation 0.2^9/0.8 ~ 6.5e-7 << 1e-3 gate

// ---------------- device scratch (no allocations allowed) ----------------
__device__ float  g_part[4*BB*EE*EE];   // 4-way k-split partial Grams
__device__ float  g_sqdist[BB*EE*EE];   // scaled sq_dist matrix
__device__ double g_psum[128];
__device__ double g_psq[128];
__device__ int    g_lbl64;              // 1 if labels buffer is int64

// ---------------- f32x2 packed helpers (Blackwell) ----------------
__device__ __forceinline__ unsigned long long pk2(float a, float b) {
    unsigned long long r;
    asm("mov.b64 %0, {%1,%2};" : "=l"(r) : "f"(a), "f"(b));
    return r;
}
__device__ __forceinline__ void unpk2(unsigned long long v, float& lo, float& hi) {
    asm("mov.b64 {%0,%1}, %2;" : "=f"(lo), "=f"(hi) : "l"(v));
}
__device__ __forceinline__ void fma2(unsigned long long& acc,
                                     unsigned long long a, unsigned long long b) {
    asm("fma.rn.f32x2 %0, %1, %2, %0;" : "+l"(acc) : "l"(a), "l"(b));
}
__device__ __forceinline__ unsigned long long add2(unsigned long long a,
                                                   unsigned long long b) {
    unsigned long long r;
    asm("add.rn.f32x2 %0, %1, %2;" : "=l"(r) : "l"(a), "l"(b));
    return r;
}

// ================= K1: partial Gram, 64x64 tile, 4x4/thread, f32x2 =====
// (round-8 version verbatim: 256 blocks, natural regalloc, 14.5us known)
__global__ void __launch_bounds__(256) k_gram(const float* __restrict__ x,
                                              const int* __restrict__ lab32) {
    __shared__ float2 sxi[64][32];
    __shared__ float2 sxj[64][32];
    int t  = threadIdx.x;
    int tx = t & 15, ty = t >> 4;
    int b  = blockIdx.z >> 2, kc = blockIdx.z & 3;
    int ib = blockIdx.y * 64, jb = blockIdx.x * 64;
    const float* xb = x + (size_t)b * EE * CC;

    // labels dtype detection (block 0 only): int64 => odd 32-bit words all 0
    if (blockIdx.x == 0 && blockIdx.y == 0 && blockIdx.z == 0) {
        __shared__ int sflag;
        if (t == 0) sflag = 0;
        __syncthreads();
        int v = 0;
        #pragma unroll
        for (int k = 0; k < 4; k++) v |= lab32[2*(t + 256*k) + 1];
        if (v) sflag = 1;
        __syncthreads();
        if (t == 0) g_lbl64 = (sflag == 0);
        __syncthreads();
    }

    unsigned long long acc[4][4];
    #pragma unroll
    for (int r = 0; r < 4; r++)
        #pragma unroll
        for (int s = 0; s < 4; s++) acc[r][s] = 0ull;

    #pragma unroll
    for (int chunk = 0; chunk < 2; chunk++) {
        int ch0 = kc * 128 + chunk * 64;
        #pragma unroll
        for (int k = 0; k < 8; k++) {
            int idx = t + k * 256;           // 2048 float2 per tile
            int row = idx >> 5, c2 = idx & 31;
            int sw  = c2 ^ ((row >> 2) & 15);
            sxi[row][sw] = *(const float2*)&xb[(ib + row) * CC + ch0 + c2 * 2];
            sxj[row][sw] = *(const float2*)&xb[(jb + row) * CC + ch0 + c2 * 2];
        }
        __syncthreads();
        #pragma unroll
        for (int c2 = 0; c2 < 32; c2++) {
            unsigned long long a2[4], b2[4];
            int ca = c2 ^ ty, cb = c2 ^ tx;
            #pragma unroll
            for (int r = 0; r < 4; r++) a2[r] = *(const unsigned long long*)&sxi[4*ty + r][ca];
            #pragma unroll
            for (int s = 0; s < 4; s++) b2[s] = *(const unsigned long long*)&sxj[4*tx + s][cb];
            #pragma unroll
            for (int r = 0; r < 4; r++)
                #pragma unroll
                for (int s = 0; s < 4; s++) fma2(acc[r][s], a2[r], b2[s]);
        }
        __syncthreads();
    }

    float* dst = g_part + (size_t)((kc * BB + b) * EE + ib + 4*ty) * EE + jb + 4*tx;
    #pragma unroll
    for (int r = 0; r < 4; r++) {
        float4 o;
        float lo, hi;
        unpk2(acc[r][0], lo, hi); o.x = lo + hi;
        unpk2(acc[r][1], lo, hi); o.y = lo + hi;
        unpk2(acc[r][2], lo, hi); o.z = lo + hi;
        unpk2(acc[r][3], lo, hi); o.w = lo + hi;
        *(float4*)(dst + (size_t)r * EE) = o;
    }
}

// ================= K2: combine partials -> sq_dist + stats partials ====
// grid (8 rowgroups, 16 batches) = 128 blocks, 512 thr: warp = row.
__global__ void __launch_bounds__(512) k_sd() {
    __shared__ float  diag[EE];
    __shared__ double sred[16], qred[16];
    int t = threadIdx.x;
    int b = blockIdx.y, rg = blockIdx.x;
    int w = t >> 5, lane = t & 31;
    int i = rg * 16 + w;
    const float rsc = 0.04419417382415922f;   // 1/sqrt(512)

    const float* gp0 = g_part + (size_t)(0*BB + b) * EE * EE;
    const float* gp1 = g_part + (size_t)(1*BB + b) * EE * EE;
    const float* gp2 = g_part + (size_t)(2*BB + b) * EE * EE;
    const float* gp3 = g_part + (size_t)(3*BB + b) * EE * EE;

    if (t < EE) {
        size_t d = (size_t)t * EE + t;
        diag[t] = (gp0[d] + gp1[d]) + (gp2[d] + gp3[d]);
    }
    __syncthreads();

    float  ni = diag[i];
    double sm = 0.0, sq = 0.0;
    float* rowp = g_sqdist + (size_t)(b * EE + i) * EE;
    #pragma unroll
    for (int k = 0; k < 4; k++) {
        int j = lane + 32*k;
        size_t off = (size_t)i * EE + j;
        float G = (gp0[off] + gp1[off]) + (gp2[off] + gp3[off]);
        float sd = (ni + diag[j] - 2.f * G) * rsc;
        rowp[j] = sd;
        if (j != i) { double d = sd; sm += d; sq += d * d; }
    }
    #pragma unroll
    for (int o = 16; o; o >>= 1) {
        sm += __shfl_xor_sync(0xffffffffu, sm, o);
        sq += __shfl_xor_sync(0xffffffffu, sq, o);
    }
    if (lane == 0) { sred[w] = sm; qred[w] = sq; }
    __syncthreads();
    if (w == 0) {
        double s2 = (lane < 16) ? sred[lane] : 0.0;
        double q2 = (lane < 16) ? qred[lane] : 0.0;
        #pragma unroll
        for (int o = 8; o; o >>= 1) {
            s2 += __shfl_xor_sync(0xffffffffu, s2, o);
            q2 += __shfl_xor_sync(0xffffffffu, q2, o);
        }
        if (lane == 0) { g_psum[b * 8 + rg] = s2; g_psq[b * 8 + rg] = q2; }
    }
}

// ================= K3: stats + weights + Neumann (per column-pair) =====
// grid (3 col-pairs, 16 batches) = 48 blocks, 256 threads: (row i, half h).
// Each block propagates [c0, c1, ones]; ones column -> local L1 norm.
// cp2's pair is (y4, ones) so only c0 is written there.
__global__ void __launch_bounds__(256)
k_prop(const int* __restrict__ lab32, float* __restrict__ out) {
    __shared__ float sh_inv;
    __shared__ __align__(16) float f[EE];
    __shared__ __align__(16) float rsp[2 * EE];
    __shared__ __align__(16) ulonglong2 v[EE];     // {c0,c1},{ones,pad}
    __shared__ __align__(16) ulonglong2 pbuf[EE];  // h1 -> h0 exchange
    int cp = blockIdx.x, b = blockIdx.y;
    int t = threadIdx.x;
    int i = t & 127, h = t >> 7;
    int base = h * 64;

    // ---- 1/std from the 128 double partials (warp 0) ----
    if (t < 32) {
        double s2 = g_psum[t] + g_psum[t + 32] + g_psum[t + 64] + g_psum[t + 96];
        double q2 = g_psq[t]  + g_psq[t + 32]  + g_psq[t + 64]  + g_psq[t + 96];
        #pragma unroll
        for (int o = 16; o; o >>= 1) {
            s2 += __shfl_xor_sync(0xffffffffu, s2, o);
            q2 += __shfl_xor_sync(0xffffffffu, q2, o);
        }
        if (t == 0) {
            const double cnt = (double)BB * EE * (EE - 1);     // mask = off-diagonal
            double var = (q2 - s2 * s2 / cnt) / (cnt - 1.0);   // Bessel (ddof=1)
            sh_inv = (float)(1.0 / sqrt(var));
        }
    }
    __syncthreads();
    float inv = sh_inv;

    // ---- W column i, rows base..base+63 (coalesced over i; W symmetric) ----
    const float* Sb = g_sqdist + (size_t)b * EE * EE;
    float s[64];
    float rs = 0.f;
    #pragma unroll
    for (int jj = 0; jj < 64; jj++) {
        int j = base + jj;
        float sd = Sb[(size_t)j * EE + i];
        float wv = (j == i) ? 0.f : expf(-sd * inv);
        s[jj] = wv;
        rs += wv;
    }
    rsp[h * EE + i] = rs;   // partial column sum == partial row sum (symmetry)
    __syncthreads();
    if (t < EE) f[t] = 0.2f / (1e-4f + rsp[t] + rsp[EE + t]);   // alpha folded
    __syncthreads();
    #pragma unroll
    for (int jj = 0; jj < 64; jj++) s[jj] *= f[base + jj];      // aS entries

    // ---- init v = [onehot c0, onehot c1, ones] ----
    int c0 = 2 * cp, c1 = 2 * cp + 1;    // c1==5 means "ones" (cp==2)
    unsigned long long a01 = 0ull, a2 = 0ull;
    if (h == 0) {
        int lbl = g_lbl64 ? lab32[2*(b*EE + i)] : lab32[b*EE + i];
        float v0 = (lbl == c0) ? 1.f : 0.f;
        float v1 = (c1 < NCL) ? ((lbl == c1) ? 1.f : 0.f) : 1.f;
        a01 = pk2(v0, v1); a2 = pk2(1.f, 0.f);
        v[i].x = a01; v[i].y = a2;
    }
    __syncthreads();

    for (int it = 0; it < KITERS; it++) {
        unsigned long long p01 = 0ull, p2 = 0ull;
        #pragma unroll
        for (int jj = 0; jj < 64; jj++) {
            ulonglong2 w = v[base + jj];         // LDS.128, warp-broadcast
            unsigned long long ssp = pk2(s[jj], s[jj]);
            fma2(p01, ssp, w.x); fma2(p2, ssp, w.y);
        }
        if (h) pbuf[i] = make_ulonglong2(p01, p2);
        __syncthreads();
        if (h == 0) {
            ulonglong2 r = pbuf[i];
            p01 = add2(p01, r.x); p2 = add2(p2, r.y);
            a01 = add2(a01, p01); a2 = add2(a2, p2);
            v[i] = make_ulonglong2(p01, p2);
        }
        __syncthreads();   // v fully updated before next iteration reads it
    }

    if (h == 0) {
        float y0, y1, l1, dummy;
        unpk2(a01, y0, y1); unpk2(a2, l1, dummy);
        float invl = 1.f / fmaxf(l1, 1e-12f);
        float* o = out + (size_t)(b*EE + i) * NCL;
        o[c0] = logf(y0 * invl + 1e-6f);
        if (c1 < NCL) o[c1] = logf(y1 * invl + 1e-6f);
    }
}

// ================= launcher =================
extern "C" void kernel_launch(void* const* d_in, const int* in_sizes, int n_in,
                              void* d_out, int out_size) {
    const float* x   = (const float*)d_in[0];
    const int*   lab = (const int*)d_in[1];   // int32 or int64 — detected on device
    float*       out = (float*)d_out;

    k_gram<<<dim3(2, 2, 64), 256>>>(x, lab);
    k_sd<<<dim3(8, BB), 512>>>();
    k_prop<<<dim3(3, BB), 256>>>(lab, out);
}